// round 5
// baseline (speedup 1.0000x reference)
#include <cuda_runtime.h>
#include <cuda_fp16.h>
#include <cstdint>

#define NN 100000
#define NE 1600000
#define NB_SCAN ((NN + 1023) / 1024)

// Static scratch (no allocations allowed)
__device__ __half g_fH[(size_t)NN * 128];  // projected features (fp16 gather payload)
__device__ float  g_fB[(size_t)NN * 128];  // inter-layer node features (fp32)
__device__ float  g_el[NN * 4];
__device__ float  g_er[NN * 4];
__device__ int    g_deg[NN];
__device__ int    g_off[NN + 1];
__device__ int    g_esrc[NE];
__device__ int    g_bsum[NB_SCAN];
__device__ int    g_boff[NB_SCAN];

// ---------------------------------------------------------------------------
// packed f32x2 helpers
__device__ __forceinline__ uint64_t dup_f32(float a) {
    uint64_t r;
    asm("mov.b64 %0, {%1, %1};" : "=l"(r) : "f"(a));
    return r;
}
__device__ __forceinline__ void fma2(uint64_t& c, uint64_t a, uint64_t b) {
    asm("fma.rn.f32x2 %0, %1, %2, %0;" : "+l"(c) : "l"(a), "l"(b));
}
__device__ __forceinline__ float2 unpk(uint64_t v) {
    float2 r;
    asm("mov.b64 {%0, %1}, %2;" : "=f"(r.x), "=f"(r.y) : "l"(v));
    return r;
}

// ===========================================================================
// CSR build: histogram -> scan -> scatter
// ===========================================================================
__global__ void hist_kernel(const int* __restrict__ dst, int* __restrict__ deg, int E) {
    int i = blockIdx.x * blockDim.x + threadIdx.x;
    if (i < E) atomicAdd(&deg[dst[i]], 1);
}

__global__ void bsum_kernel(const int* __restrict__ deg, int* __restrict__ bsum, int n) {
    __shared__ int sm[256];
    int base = blockIdx.x * 1024;
    int t = threadIdx.x;
    int s = 0;
    for (int j = 0; j < 4; j++) {
        int idx = base + t + j * 256;
        if (idx < n) s += deg[idx];
    }
    sm[t] = s;
    __syncthreads();
    for (int d = 128; d > 0; d >>= 1) {
        if (t < d) sm[t] += sm[t + d];
        __syncthreads();
    }
    if (t == 0) bsum[blockIdx.x] = sm[0];
}

__global__ void bscan_kernel(const int* __restrict__ bsum, int* __restrict__ boff,
                             int* __restrict__ off, int nb, int n) {
    __shared__ int sm[128];
    int t = threadIdx.x;
    sm[t] = (t < nb) ? bsum[t] : 0;
    __syncthreads();
    for (int d = 1; d < 128; d <<= 1) {
        int x = (t >= d) ? sm[t - d] : 0;
        __syncthreads();
        sm[t] += x;
        __syncthreads();
    }
    if (t < nb) boff[t] = (t > 0) ? sm[t - 1] : 0;
    if (t == 127) off[n] = sm[127];
}

__global__ void scan_chunk_kernel(const int* __restrict__ deg, const int* __restrict__ boff,
                                  int* __restrict__ off, int n) {
    __shared__ int sm[256];
    int base = blockIdx.x * 1024;
    int t = threadIdx.x;
    int v[4];
    int s = 0;
    for (int j = 0; j < 4; j++) {
        int idx = base + t * 4 + j;
        v[j] = (idx < n) ? deg[idx] : 0;
        s += v[j];
    }
    sm[t] = s;
    __syncthreads();
    for (int d = 1; d < 256; d <<= 1) {
        int x = (t >= d) ? sm[t - d] : 0;
        __syncthreads();
        sm[t] += x;
        __syncthreads();
    }
    int run = ((t > 0) ? sm[t - 1] : 0) + boff[blockIdx.x];
    for (int j = 0; j < 4; j++) {
        int idx = base + t * 4 + j;
        if (idx < n) off[idx] = run;
        run += v[j];
    }
}

__global__ void scatter_kernel(const int* __restrict__ src, const int* __restrict__ dst,
                               const int* __restrict__ off, int* __restrict__ cursor,
                               int* __restrict__ esrc, int E) {
    int i = blockIdx.x * blockDim.x + threadIdx.x;
    if (i >= E) return;
    int dn = dst[i];
    int pos = off[dn] + atomicAdd(&cursor[dn], 1);
    esrc[pos] = src[i];
}

// ===========================================================================
// Fused GEMM + attention scores: F(half) = X @ W; el/er from fp32 result.
// A-tile stored transposed in smem: Xs[k][r] -> one LDS.128 per k.
// BR=64 rows/block, thread tile 4 rows x 8 cols, blockDim = 16*(COLS/8).
// ===========================================================================
template <int COLS, int H>
__global__ void gemm_attn_kernel(const float* __restrict__ X, const float* __restrict__ W,
                                 const float* __restrict__ al, const float* __restrict__ ar,
                                 __half* __restrict__ F, float* __restrict__ el,
                                 float* __restrict__ er, int nrows) {
    constexpr int K    = 128;
    constexpr int BR   = 64;
    constexpr int XPAD = BR + 4;     // float4-aligned row stride
    extern __shared__ float sm[];
    float* Xs = sm;                  // [K][XPAD], transposed
    float* Ws = sm + K * XPAD;       // [K][COLS]

    const int tid  = threadIdx.x;
    const int nth  = blockDim.x;
    const int row0 = blockIdx.x * BR;

    for (int i = tid; i < K * COLS / 4; i += nth)
        ((float4*)Ws)[i] = ((const float4*)W)[i];

    for (int i = tid; i < BR * (K / 4); i += nth) {
        int r  = i / (K / 4);
        int k4 = i % (K / 4);
        int row = row0 + r;
        float4 v = make_float4(0.f, 0.f, 0.f, 0.f);
        if (row < nrows) v = ((const float4*)(X + (size_t)row * K))[k4];
        Xs[(k4 * 4 + 0) * XPAD + r] = v.x;
        Xs[(k4 * 4 + 1) * XPAD + r] = v.y;
        Xs[(k4 * 4 + 2) * XPAD + r] = v.z;
        Xs[(k4 * 4 + 3) * XPAD + r] = v.w;
    }
    __syncthreads();

    const int rc = tid % 16;
    const int cc = tid / 16;

    uint64_t acc2[4][4] = {};

#pragma unroll 4
    for (int k = 0; k < K; k++) {
        float4 a4 = *(const float4*)&Xs[k * XPAD + rc * 4];
        const ulonglong2* bp = (const ulonglong2*)&Ws[k * COLS + cc * 8];
        ulonglong2 b01 = bp[0];
        ulonglong2 b23 = bp[1];
        uint64_t a0 = dup_f32(a4.x), a1 = dup_f32(a4.y);
        uint64_t a2 = dup_f32(a4.z), a3 = dup_f32(a4.w);
        fma2(acc2[0][0], a0, b01.x); fma2(acc2[0][1], a0, b01.y);
        fma2(acc2[0][2], a0, b23.x); fma2(acc2[0][3], a0, b23.y);
        fma2(acc2[1][0], a1, b01.x); fma2(acc2[1][1], a1, b01.y);
        fma2(acc2[1][2], a1, b23.x); fma2(acc2[1][3], a1, b23.y);
        fma2(acc2[2][0], a2, b01.x); fma2(acc2[2][1], a2, b01.y);
        fma2(acc2[2][2], a2, b23.x); fma2(acc2[2][3], a2, b23.y);
        fma2(acc2[3][0], a3, b01.x); fma2(acc2[3][1], a3, b01.y);
        fma2(acc2[3][2], a3, b23.x); fma2(acc2[3][3], a3, b23.y);
    }

    float al8[8], ar8[8];
#pragma unroll
    for (int j = 0; j < 8; j++) {
        al8[j] = __ldg(al + cc * 8 + j);
        ar8[j] = __ldg(ar + cc * 8 + j);
    }

    float slp[4], srp[4];
#pragma unroll
    for (int i = 0; i < 4; i++) {
        float o[8];
#pragma unroll
        for (int j2 = 0; j2 < 4; j2++) {
            float2 p = unpk(acc2[i][j2]);
            o[2 * j2] = p.x; o[2 * j2 + 1] = p.y;
        }
        int row = row0 + rc * 4 + i;
        if (row < nrows) {
            __half2 h0 = __floats2half2_rn(o[0], o[1]);
            __half2 h1 = __floats2half2_rn(o[2], o[3]);
            __half2 h2 = __floats2half2_rn(o[4], o[5]);
            __half2 h3 = __floats2half2_rn(o[6], o[7]);
            uint4 u;
            u.x = *(uint32_t*)&h0; u.y = *(uint32_t*)&h1;
            u.z = *(uint32_t*)&h2; u.w = *(uint32_t*)&h3;
            *(uint4*)(F + (size_t)row * COLS + cc * 8) = u;
        }
        float sl = 0.f, sr = 0.f;
#pragma unroll
        for (int j = 0; j < 8; j++) { sl = fmaf(o[j], al8[j], sl); sr = fmaf(o[j], ar8[j], sr); }
        slp[i] = sl; srp[i] = sr;
    }

    __syncthreads();
    float* red = sm;            // [BR][H][2]
    for (int i = tid; i < BR * H * 2; i += nth) red[i] = 0.f;
    __syncthreads();
    int h = (H == 1) ? 0 : (cc * 8) / 32;
#pragma unroll
    for (int i = 0; i < 4; i++) {
        int r = rc * 4 + i;
        atomicAdd(&red[(r * H + h) * 2 + 0], slp[i]);
        atomicAdd(&red[(r * H + h) * 2 + 1], srp[i]);
    }
    __syncthreads();
    for (int i = tid; i < BR * H; i += nth) {
        int r = i / H, hh = i % H;
        int row = row0 + r;
        if (row < nrows) {
            el[row * H + hh] = red[i * 2 + 0];
            er[row * H + hh] = red[i * 2 + 1];
        }
    }
}

// ===========================================================================
// CSR edge aggregation + fused normalize/bias/ELU. One warp per dst node.
// w = exp(leakyrelu(el[src]+er[dst])) per head (segment-max shift dropped:
// alpha = w/s invariant; scores O(1)). F payload is fp16.
// ===========================================================================
template <int H, bool ELU>
__global__ void edge_csr_kernel(const __half* __restrict__ F, const float* __restrict__ el,
                                const float* __restrict__ er, const int* __restrict__ off,
                                const int* __restrict__ esrc, const float* __restrict__ b,
                                float* __restrict__ out, int n) {
    constexpr int HD = H * 32;
    int warp = (blockIdx.x * blockDim.x + threadIdx.x) >> 5;
    int lane = threadIdx.x & 31;
    if (warp >= n) return;
    const int node = warp;

    float erh;
    if (H == 4) {
        float4 e4 = *(const float4*)(er + node * 4);
        erh = lane < 8 ? e4.x : lane < 16 ? e4.y : lane < 24 ? e4.z : e4.w;
    } else {
        erh = __ldg(er + node);
    }

    const int start = off[node], end = off[node + 1];
    float acc0 = 0.f, acc1 = 0.f, acc2 = 0.f, acc3 = 0.f, s = 0.f;

    for (int base = start; base < end; base += 32) {
        int cnt = min(32, end - base);
        int sidx = (base + lane < end) ? __ldg(esrc + base + lane) : 0;
#pragma unroll 4
        for (int j = 0; j < cnt; j++) {
            int sn = __shfl_sync(0xffffffffu, sidx, j);
            float elh;
            if (H == 4) {
                float4 e4 = *(const float4*)(el + sn * 4);
                elh = lane < 8 ? e4.x : lane < 16 ? e4.y : lane < 24 ? e4.z : e4.w;
            } else {
                elh = __ldg(el + sn);
            }
            float v = elh + erh;
            v = v > 0.f ? v : 0.2f * v;
            float w = __expf(v);
            s += w;
            if (H == 4) {
                uint2 p = *(const uint2*)(F + (size_t)sn * 128 + lane * 4);
                float2 f0 = __half22float2(*(__half2*)&p.x);
                float2 f1 = __half22float2(*(__half2*)&p.y);
                acc0 = fmaf(w, f0.x, acc0);
                acc1 = fmaf(w, f0.y, acc1);
                acc2 = fmaf(w, f1.x, acc2);
                acc3 = fmaf(w, f1.y, acc3);
            } else {
                float f = __half2float(__ldg(F + (size_t)sn * 32 + lane));
                acc0 = fmaf(w, f, acc0);
            }
        }
    }

    float inv = 1.f / fmaxf(s, 1e-9f);
    if (H == 4) {
        int c = lane * 4;
        float4 o;
        o.x = acc0 * inv + b[c + 0];
        o.y = acc1 * inv + b[c + 1];
        o.z = acc2 * inv + b[c + 2];
        o.w = acc3 * inv + b[c + 3];
        if (ELU) {
            o.x = o.x > 0.f ? o.x : expm1f(o.x);
            o.y = o.y > 0.f ? o.y : expm1f(o.y);
            o.z = o.z > 0.f ? o.z : expm1f(o.z);
            o.w = o.w > 0.f ? o.w : expm1f(o.w);
        }
        *(float4*)(out + (size_t)node * HD + c) = o;
    } else {
        float o = acc0 * inv + b[lane];
        if (ELU) o = o > 0.f ? o : expm1f(o);
        out[(size_t)node * HD + lane] = o;
    }
}

// ===========================================================================
extern "C" void kernel_launch(void* const* d_in, const int* in_sizes, int n_in,
                              void* d_out, int out_size) {
    const float* x   = (const float*)d_in[0];
    const int*   src = (const int*)d_in[1];
    const int*   dst = (const int*)d_in[2];
    const float* W1  = (const float*)d_in[3];
    const float* al1 = (const float*)d_in[4];
    const float* ar1 = (const float*)d_in[5];
    const float* b1  = (const float*)d_in[6];
    const float* W2  = (const float*)d_in[7];
    const float* al2 = (const float*)d_in[8];
    const float* ar2 = (const float*)d_in[9];
    const float* b2  = (const float*)d_in[10];
    const float* W3  = (const float*)d_in[11];
    const float* al3 = (const float*)d_in[12];
    const float* ar3 = (const float*)d_in[13];
    const float* b3  = (const float*)d_in[14];
    float* out = (float*)d_out;

    const int N = in_sizes[0] / 128;
    const int E = in_sizes[1];

    __half* fH;
    float *fB, *el, *er;
    int *deg, *off, *esrc, *bsum, *boff;
    cudaGetSymbolAddress((void**)&fH, g_fH);
    cudaGetSymbolAddress((void**)&fB, g_fB);
    cudaGetSymbolAddress((void**)&el, g_el);
    cudaGetSymbolAddress((void**)&er, g_er);
    cudaGetSymbolAddress((void**)&deg, g_deg);
    cudaGetSymbolAddress((void**)&off, g_off);
    cudaGetSymbolAddress((void**)&esrc, g_esrc);
    cudaGetSymbolAddress((void**)&bsum, g_bsum);
    cudaGetSymbolAddress((void**)&boff, g_boff);

    const int SMEM128 = (128 * 68 + 128 * 128) * (int)sizeof(float);
    const int SMEM32  = (128 * 68 + 128 * 32)  * (int)sizeof(float);
    cudaFuncSetAttribute((const void*)gemm_attn_kernel<128, 4>,
                         cudaFuncAttributeMaxDynamicSharedMemorySize, SMEM128);
    cudaFuncSetAttribute((const void*)gemm_attn_kernel<32, 1>,
                         cudaFuncAttributeMaxDynamicSharedMemorySize, SMEM32);

    const int gemm_blocks = (N + 63) / 64;
    const int eblk = (E + 255) / 256;
    const int nb   = (N + 1023) / 1024;
    const int edge_blocks = (N * 32 + 255) / 256;

    // ---------------- CSR build (reused by all 3 layers) ----------------
    cudaMemsetAsync(deg, 0, (size_t)N * sizeof(int));
    hist_kernel<<<eblk, 256>>>(dst, deg, E);
    bsum_kernel<<<nb, 256>>>(deg, bsum, N);
    bscan_kernel<<<1, 128>>>(bsum, boff, off, nb, N);
    scan_chunk_kernel<<<nb, 256>>>(deg, boff, off, N);
    cudaMemsetAsync(deg, 0, (size_t)N * sizeof(int));
    scatter_kernel<<<eblk, 256>>>(src, dst, off, deg, esrc, E);

    // ---------------- Layer 1 ----------------
    gemm_attn_kernel<128, 4><<<gemm_blocks, 256, SMEM128>>>(
        x, W1, al1, ar1, fH, el, er, N);
    edge_csr_kernel<4, true><<<edge_blocks, 256>>>(fH, el, er, off, esrc, b1, fB, N);

    // ---------------- Layer 2 ----------------
    gemm_attn_kernel<128, 4><<<gemm_blocks, 256, SMEM128>>>(
        fB, W2, al2, ar2, fH, el, er, N);
    edge_csr_kernel<4, true><<<edge_blocks, 256>>>(fH, el, er, off, esrc, b2, fB, N);

    // ---------------- Layer 3 ----------------
    gemm_attn_kernel<32, 1><<<gemm_blocks, 64, SMEM32>>>(
        fB, W3, al3, ar3, fH, el, er, N);
    edge_csr_kernel<1, false><<<edge_blocks, 256>>>(fH, el, er, off, esrc, b3, out, N);
}